// round 5
// baseline (speedup 1.0000x reference)
#include <cuda_runtime.h>

#define CK __restrict__
typedef unsigned long long ull;

// ---------------- f32x2 helpers (packed fp32 pipe, sm_103a) ----------------
__device__ __forceinline__ ull pack2(float lo, float hi) {
    ull r; asm("mov.b64 %0, {%1, %2};" : "=l"(r) : "f"(lo), "f"(hi)); return r;
}
__device__ __forceinline__ void unpack2(ull v, float& lo, float& hi) {
    asm("mov.b64 {%0, %1}, %2;" : "=f"(lo), "=f"(hi) : "l"(v));
}
__device__ __forceinline__ void ffma2(ull& d, ull a, ull b) {
    asm("fma.rn.f32x2 %0, %1, %2, %0;" : "+l"(d) : "l"(a), "l"(b));
}
__device__ __forceinline__ ull mul2(ull a, ull b) {
    ull r; asm("mul.rn.f32x2 %0, %1, %2;" : "=l"(r) : "l"(a), "l"(b)); return r;
}
__device__ __forceinline__ ull add2(ull a, ull b) {
    ull r; asm("add.rn.f32x2 %0, %1, %2;" : "=l"(r) : "l"(a), "l"(b)); return r;
}

// ---------------- scratch (device globals: allocation-free) ----------------
__device__ float g_y [4*128*128*128];                 // deconv output (incl. bias)
__device__ float g_kf[4*9*128*128];                   // PAC gaussian factors
__device__ __align__(16) float g_w1d[4*256*128*4*2];  // w1 repacked+dup: [p][ci][co][tap][2]
__device__ __align__(16) float g_w2d[128*9*128*2];    // wk repacked+dup: [c][ij][o][2]

// ---------------- weight prep ----------------
// deconv tap math: oh = 2*ih - 1 + kh.  For output parity pr (oh = 2R+pr):
//   tap0,1 -> input row (smem r+1), kh = 1-pr ; tap2,3 -> input row (smem r), kh = 3-pr
//   within a tap pair: tap even -> col+1 (kw = 1-ps), tap odd -> col (kw = 3-ps)
__global__ void prep_weights_kernel(const float* CK w1, const float* CK w2) {
    int idx = blockIdx.x * blockDim.x + threadIdx.x;
    const int n1 = 4*256*128*4;
    if (idx < n1) {
        int t  = idx & 3;
        int co = (idx >> 2) & 127;
        int ci = (idx >> 9) & 255;
        int p  = idx >> 17;
        int pr = p >> 1, ps = p & 1;
        int th = t >> 1, tw = t & 1;
        int kh = 2*th + 1 - pr;
        int kw = 2*tw + 1 - ps;
        float v = w1[((ci*128 + co)*4 + kh)*4 + kw];
        g_w1d[idx*2]   = v;   // duplicated pair for f32x2 broadcast
        g_w1d[idx*2+1] = v;
    }
    const int n2 = 128*9*128;
    if (idx < n2) {
        int o  = idx & 127;
        int ij = (idx >> 7) % 9;
        int c  = idx / (9*128);
        int i = ij / 3, j = ij % 3;
        float v = w2[((c*128 + o)*3 + (2 - i))*3 + (2 - j)];  // wk[o,c,i,j]=w2[c,o,2-i,2-j]
        g_w2d[idx*2]   = v;
        g_w2d[idx*2+1] = v;
    }
}

// ---------------- stage 1: conv_transpose 4x4 s2 p1 (f32x2) ----------------
// Per parity class (pr,ps): effective 2x2 stride-1 conv on the 64x64 input.
// Block: 64 co x (8R x 32S) outputs of one parity. Thread: 8co x 8sp (4 f32x2 pairs).
static const int DC_XS_BYTES = 16*9*34*4;            // 19584
static const int DC_WS_BYTES = 16*64*4*8;            // 32768 (ull pairs)
static const int DC_SMEM     = DC_XS_BYTES + DC_WS_BYTES;

__global__ __launch_bounds__(256, 2)
void deconv_kernel(const float* CK x, const float* CK b1) {
    extern __shared__ unsigned char smem_raw[];
    float (*xs)[9][34]  = (float(*)[9][34])smem_raw;
    ull   (*ws)[64][4]  = (ull(*)[64][4])(smem_raw + DC_XS_BYTES);

    const int tid = threadIdx.x;
    const int rt = blockIdx.x >> 1;
    const int st = blockIdx.x & 1;
    const int R0 = rt * 8, S0 = st * 32;
    const int p   = blockIdx.y >> 1;
    const int co0 = (blockIdx.y & 1) * 64;
    const int pr = p >> 1, ps = p & 1;
    const int b = blockIdx.z;

    const int cg8 = tid >> 5;          // 8 co-groups of 8
    const int pg  = tid & 31;
    const int r   = pg >> 2;           // 0..7
    const int s8  = (pg & 3) * 8;      // 0,8,16,24

    ull acc[8][4];
#pragma unroll
    for (int a = 0; a < 8; a++)
#pragma unroll
        for (int q = 0; q < 4; q++) acc[a][q] = 0ull;

    const int rowbase = R0 - (1 - pr);
    const int colbase = S0 - (1 - ps);

    for (int ch = 0; ch < 16; ch++) {
        const int ci0 = ch * 16;
        // x halo tile (zero padded at border); 34 cols: s8 max 24 + 9 offset
        for (int e = tid; e < 16*9*34; e += 256) {
            int col = e % 34;
            int tmp = e / 34;
            int row = tmp % 9;
            int cc  = tmp / 9;
            int gr = rowbase + row, gc = colbase + col;
            float v = 0.f;
            if ((unsigned)gr < 64u && (unsigned)gc < 64u)
                v = x[((b*256 + ci0 + cc)*64 + gr)*64 + gc];
            xs[cc][row][col] = v;
        }
        // duplicated weight pairs (contiguous 512-float rows per ci)
        {
            const ull* wsrc = (const ull*)&g_w1d[((size_t)(p*256 + ci0)*128 + co0)*8];
            ull* wdst = &ws[0][0][0];
            for (int e = tid; e < 16*256; e += 256) {
                int cc = e >> 8;
                int rest = e & 255;
                wdst[cc*256 + rest] = wsrc[cc*512 + rest];
            }
        }
        __syncthreads();

#pragma unroll 1
        for (int cc = 0; cc < 16; cc++) {
            float xh[10], xl[10];
#pragma unroll
            for (int j = 0; j < 10; j++) {
                xh[j] = xs[cc][r + 1][s8 + j];
                xl[j] = xs[cc][r    ][s8 + j];
            }
            ull xh0[4], xh1[4], xl0[4], xl1[4];
#pragma unroll
            for (int q = 0; q < 4; q++) {
                xh0[q] = pack2(xh[2*q],   xh[2*q+1]);
                xh1[q] = pack2(xh[2*q+1], xh[2*q+2]);
                xl0[q] = pack2(xl[2*q],   xl[2*q+1]);
                xl1[q] = pack2(xl[2*q+1], xl[2*q+2]);
            }
#pragma unroll
            for (int cg = 0; cg < 8; cg++) {
                const ull* wp = &ws[cc][cg8*8 + cg][0];
                ull w0 = wp[0], w1 = wp[1], w2 = wp[2], w3 = wp[3];
#pragma unroll
                for (int q = 0; q < 4; q++) {
                    ffma2(acc[cg][q], w0, xh1[q]);
                    ffma2(acc[cg][q], w1, xh0[q]);
                    ffma2(acc[cg][q], w2, xl1[q]);
                    ffma2(acc[cg][q], w3, xl0[q]);
                }
            }
        }
        __syncthreads();
    }

    // epilogue: y = acc + b1 (stride-2 scatter into full-res y)
#pragma unroll
    for (int cg = 0; cg < 8; cg++) {
        int co = co0 + cg8*8 + cg;
        float bv = b1[co];
        int oh = 2*(R0 + r) + pr;
        float* dst = &g_y[((b*128 + co)*128 + oh)*128];
#pragma unroll
        for (int q = 0; q < 4; q++) {
            float lo, hi;
            unpack2(acc[cg][q], lo, hi);
            dst[2*(S0 + s8 + 2*q)     + ps] = lo + bv;
            dst[2*(S0 + s8 + 2*q + 1) + ps] = hi + bv;
        }
    }
}

// ---------------- stage 2a: gaussian kernel factors ----------------
// kf[b,ij,h,w] = exp(-0.5 * sum_c (gpad[c,h+i-1,w+j-1] - g[c,h,w])^2)
__global__ __launch_bounds__(256)
void kfac_kernel(const float* CK guide) {
    const int tid = threadIdx.x;
    const int b = blockIdx.z;
    const int H0 = (blockIdx.x >> 3) * 16;
    const int W0 = (blockIdx.x & 7) * 16;
    __shared__ float gs[16][18][19];
    const int r  = tid >> 4;
    const int sc = tid & 15;
    float acc[9];
#pragma unroll
    for (int k = 0; k < 9; k++) acc[k] = 0.f;

    for (int ch = 0; ch < 8; ch++) {
        const int c0 = ch * 16;
        for (int e = tid; e < 16*18*18; e += 256) {
            int col = e % 18;
            int tmp = e / 18;
            int row = tmp % 18;
            int cc  = tmp / 18;
            int gr = H0 - 1 + row, gc = W0 - 1 + col;
            float v = 0.f;
            if ((unsigned)gr < 128u && (unsigned)gc < 128u)
                v = guide[((b*128 + c0 + cc)*128 + gr)*128 + gc];
            gs[cc][row][col] = v;
        }
        __syncthreads();
#pragma unroll 1
        for (int cc = 0; cc < 16; cc++) {
            float gc0 = gs[cc][r + 1][sc + 1];
#pragma unroll
            for (int ij = 0; ij < 9; ij++) {
                int di = ij / 3, dj = ij % 3;
                float d = gs[cc][r + di][sc + dj] - gc0;
                acc[ij] += d * d;
            }
        }
        __syncthreads();
    }
#pragma unroll
    for (int ij = 0; ij < 9; ij++)
        g_kf[((b*9 + ij)*128 + H0 + r)*128 + W0 + sc] = expf(-0.5f * acc[ij]);
}

// ---------------- stage 2b: PAC main (9-tap scaled conv, f32x2) ----------------
// Block: 64 co x (16x16) spatial tile. Thread: 8co x 8pos (4 f32x2 pairs).
static const int PC_YS_BYTES = 8*18*20*4;            // 11520 (rows padded to 20 for LDS.64)
static const int PC_KS_BYTES = 9*16*18*4;            // 10368 (rows padded to 18)
static const int PC_WS_BYTES = 8*9*64*8;             // 36864 (ull pairs)
static const int PC_SMEM     = PC_YS_BYTES + PC_KS_BYTES + PC_WS_BYTES;

__global__ __launch_bounds__(256, 2)
void pac_kernel(const float* CK b2, float* CK out) {
    extern __shared__ unsigned char smem_raw[];
    float (*ysm)[18][20] = (float(*)[18][20])smem_raw;
    float (*ksm)[16][18] = (float(*)[16][18])(smem_raw + PC_YS_BYTES);
    ull   (*wsm)[9][64]  = (ull(*)[9][64])(smem_raw + PC_YS_BYTES + PC_KS_BYTES);

    const int tid = threadIdx.x;
    const int b = blockIdx.z;
    const int co0 = blockIdx.y * 64;
    const int H0 = (blockIdx.x >> 3) * 16;
    const int W0 = (blockIdx.x & 7) * 16;

    const int cg8 = tid >> 5;
    const int pg  = tid & 31;
    const int r   = pg >> 1;           // 0..15
    const int sc8 = (pg & 1) * 8;      // 0,8

    // gaussian factors for tile (once)
    for (int e = tid; e < 9*256; e += 256) {
        int cc = e & 255;
        int ij = e >> 8;
        int rr = cc >> 4, col = cc & 15;
        ksm[ij][rr][col] = g_kf[((b*9 + ij)*128 + H0 + rr)*128 + W0 + col];
    }

    ull acc[8][4];
#pragma unroll
    for (int a = 0; a < 8; a++)
#pragma unroll
        for (int q = 0; q < 4; q++) acc[a][q] = 0ull;

    for (int ch = 0; ch < 16; ch++) {
        const int c0 = ch * 8;
        // y halo tile (18 cols used, rows padded to 20 floats for 8B alignment)
        for (int e = tid; e < 8*18*18; e += 256) {
            int col = e % 18;
            int tmp = e / 18;
            int row = tmp % 18;
            int cc  = tmp / 18;
            int gr = H0 - 1 + row, gc = W0 - 1 + col;
            float v = 0.f;
            if ((unsigned)gr < 128u && (unsigned)gc < 128u)
                v = g_y[((b*128 + c0 + cc)*128 + gr)*128 + gc];
            ysm[cc][row][col] = v;
        }
        // duplicated weight pairs
        {
            const ull* wsrc = ((const ull*)g_w2d) + (size_t)(c0*9)*128 + co0;
            for (int e = tid; e < 8*9*64; e += 256) {
                int ol = e & 63;
                int ij = (e >> 6) % 9;
                int cc = e / (9*64);
                wsm[cc][ij][ol] = wsrc[((size_t)cc*9 + ij)*128 + ol];
            }
        }
        __syncthreads();

#pragma unroll
        for (int ij = 0; ij < 9; ij++) {
            const int di = ij / 3, dj = ij % 3;
            ull kp[4];
#pragma unroll
            for (int q = 0; q < 4; q++)
                kp[q] = *(const ull*)&ksm[ij][r][sc8 + 2*q];
#pragma unroll
            for (int cc = 0; cc < 8; cc++) {
                const float* yrow = &ysm[cc][r + di][sc8 + dj];
                ull t[4];
                if (dj == 1) {
                    // odd alignment: scalar loads + packs
#pragma unroll
                    for (int q = 0; q < 4; q++)
                        t[q] = mul2(pack2(yrow[2*q], yrow[2*q+1]), kp[q]);
                } else {
                    // even alignment: direct LDS.64
#pragma unroll
                    for (int q = 0; q < 4; q++)
                        t[q] = mul2(*(const ull*)(yrow + 2*q), kp[q]);
                }
#pragma unroll
                for (int cg = 0; cg < 8; cg++) {
                    ull w = wsm[cc][ij][cg8*8 + cg];   // broadcast LDS.64
#pragma unroll
                    for (int q = 0; q < 4; q++)
                        ffma2(acc[cg][q], w, t[q]);
                }
            }
        }
        __syncthreads();
    }

    // epilogue: out = acc + b2 (STG.64 pairs)
#pragma unroll
    for (int cg = 0; cg < 8; cg++) {
        int co = co0 + cg8*8 + cg;
        float bv = b2[co];
        ull bvd = pack2(bv, bv);
        float* dst = &out[((size_t)(b*128 + co)*128 + H0 + r)*128 + W0 + sc8];
#pragma unroll
        for (int q = 0; q < 4; q++)
            *(ull*)(dst + 2*q) = add2(acc[cg][q], bvd);
    }
}

// ---------------- launch ----------------
extern "C" void kernel_launch(void* const* d_in, const int* in_sizes, int n_in,
                              void* d_out, int out_size) {
    const float* x     = (const float*)d_in[0];
    const float* guide = (const float*)d_in[1];
    const float* w1    = (const float*)d_in[2];
    const float* b1    = (const float*)d_in[3];
    const float* w2    = (const float*)d_in[4];
    const float* b2    = (const float*)d_in[5];
    float* out = (float*)d_out;

    cudaFuncSetAttribute(deconv_kernel, cudaFuncAttributeMaxDynamicSharedMemorySize, DC_SMEM);
    cudaFuncSetAttribute(pac_kernel,    cudaFuncAttributeMaxDynamicSharedMemorySize, PC_SMEM);

    prep_weights_kernel<<<(4*256*128*4 + 255)/256, 256>>>(w1, w2);
    deconv_kernel<<<dim3(16, 8, 4), 256, DC_SMEM>>>(x, b1);
    kfac_kernel<<<dim3(64, 1, 4), 256>>>(guide);
    pac_kernel<<<dim3(64, 2, 4), 256, PC_SMEM>>>(b2, out);
}

// round 6
// speedup vs baseline: 1.1845x; 1.1845x over previous
#include <cuda_runtime.h>

#define CK __restrict__
typedef unsigned long long ull;

// ---------------- f32x2 helpers (packed fp32 pipe, sm_103a) ----------------
__device__ __forceinline__ ull pack2(float lo, float hi) {
    ull r; asm("mov.b64 %0, {%1, %2};" : "=l"(r) : "f"(lo), "f"(hi)); return r;
}
__device__ __forceinline__ void unpack2(ull v, float& lo, float& hi) {
    asm("mov.b64 {%0, %1}, %2;" : "=f"(lo), "=f"(hi) : "l"(v));
}
__device__ __forceinline__ void ffma2(ull& d, ull a, ull b) {
    asm("fma.rn.f32x2 %0, %1, %2, %0;" : "+l"(d) : "l"(a), "l"(b));
}
__device__ __forceinline__ ull mul2(ull a, ull b) {
    ull r; asm("mul.rn.f32x2 %0, %1, %2;" : "=l"(r) : "l"(a), "l"(b)); return r;
}
__device__ __forceinline__ ull add2(ull a, ull b) {
    ull r; asm("add.rn.f32x2 %0, %1, %2;" : "=l"(r) : "l"(a), "l"(b)); return r;
}

// ---------------- scratch (device globals: allocation-free) ----------------
__device__ float g_y [4*128*128*128];                 // deconv output (incl. bias)
__device__ float g_kf[4*9*128*128];                   // PAC gaussian factors
__device__ __align__(16) float g_w1d[4*256*128*4*2];  // w1 repacked+dup: [p][ci][co][tap][2]
__device__ __align__(16) float g_w2d[128*9*128*2];    // wk repacked+dup: [c][ij][o][2]

// ---------------- weight prep ----------------
// deconv tap math: oh = 2*ih - 1 + kh.  For output parity pr (oh = 2R+pr):
//   tap0,1 -> input row (smem r+1), kh = 1-pr ; tap2,3 -> input row (smem r), kh = 3-pr
//   within a tap pair: tap even -> col+1 (kw = 1-ps), tap odd -> col (kw = 3-ps)
__global__ void prep_weights_kernel(const float* CK w1, const float* CK w2) {
    int idx = blockIdx.x * blockDim.x + threadIdx.x;
    const int n1 = 4*256*128*4;
    if (idx < n1) {
        int t  = idx & 3;
        int co = (idx >> 2) & 127;
        int ci = (idx >> 9) & 255;
        int p  = idx >> 17;
        int pr = p >> 1, ps = p & 1;
        int th = t >> 1, tw = t & 1;
        int kh = 2*th + 1 - pr;
        int kw = 2*tw + 1 - ps;
        float v = w1[((ci*128 + co)*4 + kh)*4 + kw];
        g_w1d[idx*2]   = v;   // duplicated pair for f32x2 broadcast
        g_w1d[idx*2+1] = v;
    }
    const int n2 = 128*9*128;
    if (idx < n2) {
        int o  = idx & 127;
        int ij = (idx >> 7) % 9;
        int c  = idx / (9*128);
        int i = ij / 3, j = ij % 3;
        float v = w2[((c*128 + o)*3 + (2 - i))*3 + (2 - j)];  // wk[o,c,i,j]=w2[c,o,2-i,2-j]
        g_w2d[idx*2]   = v;
        g_w2d[idx*2+1] = v;
    }
}

// ---------------- stage 1: conv_transpose 4x4 s2 p1 (f32x2) ----------------
// Per parity class (pr,ps): effective 2x2 stride-1 conv on the 64x64 input.
// Block: 64 co x (8R x 32S) outputs of one parity. Thread: 8co x 8sp (4 f32x2 pairs).
// xs (even) plus xs_odd (shifted by one col) so ALL pair loads are aligned LDS.64.
static const int DC_XS_BYTES = 16*9*34*4;            // 19584
static const int DC_SMEM     = 2*DC_XS_BYTES + 16*64*4*8;  // 39168 + 32768 = 71936

__global__ __launch_bounds__(256, 2)
void deconv_kernel(const float* CK x, const float* CK b1) {
    extern __shared__ unsigned char smem_raw[];
    float (*xs)[9][34]   = (float(*)[9][34])smem_raw;
    float (*xso)[9][34]  = (float(*)[9][34])(smem_raw + DC_XS_BYTES);
    ull   (*ws)[64][4]   = (ull(*)[64][4])(smem_raw + 2*DC_XS_BYTES);

    const int tid = threadIdx.x;
    const int rt = blockIdx.x >> 1;
    const int st = blockIdx.x & 1;
    const int R0 = rt * 8, S0 = st * 32;
    const int p   = blockIdx.y >> 1;
    const int co0 = (blockIdx.y & 1) * 64;
    const int pr = p >> 1, ps = p & 1;
    const int b = blockIdx.z;

    const int cg8 = tid >> 5;          // 8 co-groups of 8
    const int pg  = tid & 31;
    const int r   = pg >> 2;           // 0..7
    const int s8  = (pg & 3) * 8;      // 0,8,16,24

    ull acc[8][4];
#pragma unroll
    for (int a = 0; a < 8; a++)
#pragma unroll
        for (int q = 0; q < 4; q++) acc[a][q] = 0ull;

    const int rowbase = R0 - (1 - pr);
    const int colbase = S0 - (1 - ps);

    for (int ch = 0; ch < 16; ch++) {
        const int ci0 = ch * 16;
        // x halo tile (zero padded at border); dual store: xs + shifted copy
        for (int e = tid; e < 16*9*34; e += 256) {
            int col = e % 34;
            int tmp = e / 34;
            int row = tmp % 9;
            int cc  = tmp / 9;
            int gr = rowbase + row, gc = colbase + col;
            float v = 0.f;
            if ((unsigned)gr < 64u && (unsigned)gc < 64u)
                v = x[((b*256 + ci0 + cc)*64 + gr)*64 + gc];
            xs[cc][row][col] = v;
            if (col >= 1) xso[cc][row][col - 1] = v;
        }
        // duplicated weight pairs (contiguous 512-float rows per ci)
        {
            const ull* wsrc = (const ull*)&g_w1d[((size_t)(p*256 + ci0)*128 + co0)*8];
            ull* wdst = &ws[0][0][0];
            for (int e = tid; e < 16*256; e += 256) {
                int cc = e >> 8;
                int rest = e & 255;
                wdst[cc*256 + rest] = wsrc[cc*512 + rest];
            }
        }
        __syncthreads();

#pragma unroll 1
        for (int cc = 0; cc < 16; cc++) {
            const ull* ph  = (const ull*)&xs [cc][r + 1][s8];
            const ull* phO = (const ull*)&xso[cc][r + 1][s8];
            const ull* pl  = (const ull*)&xs [cc][r    ][s8];
            const ull* plO = (const ull*)&xso[cc][r    ][s8];
            ull xh0[4], xh1[4], xl0[4], xl1[4];
#pragma unroll
            for (int q = 0; q < 4; q++) {
                xh0[q] = ph [q];   // (x[2q],   x[2q+1])
                xh1[q] = phO[q];   // (x[2q+1], x[2q+2])
                xl0[q] = pl [q];
                xl1[q] = plO[q];
            }
#pragma unroll
            for (int cg = 0; cg < 8; cg++) {
                const ull* wp = &ws[cc][cg8*8 + cg][0];
                ull w0 = wp[0], w1 = wp[1], w2 = wp[2], w3 = wp[3];
#pragma unroll
                for (int q = 0; q < 4; q++) {
                    ffma2(acc[cg][q], w0, xh1[q]);
                    ffma2(acc[cg][q], w1, xh0[q]);
                    ffma2(acc[cg][q], w2, xl1[q]);
                    ffma2(acc[cg][q], w3, xl0[q]);
                }
            }
        }
        __syncthreads();
    }

    // epilogue: y = acc + b1 (stride-2 scatter into full-res y)
#pragma unroll
    for (int cg = 0; cg < 8; cg++) {
        int co = co0 + cg8*8 + cg;
        float bv = b1[co];
        int oh = 2*(R0 + r) + pr;
        float* dst = &g_y[((b*128 + co)*128 + oh)*128];
#pragma unroll
        for (int q = 0; q < 4; q++) {
            float lo, hi;
            unpack2(acc[cg][q], lo, hi);
            dst[2*(S0 + s8 + 2*q)     + ps] = lo + bv;
            dst[2*(S0 + s8 + 2*q + 1) + ps] = hi + bv;
        }
    }
}

// ---------------- stage 2a: gaussian kernel factors ----------------
// kf[b,ij,h,w] = exp(-0.5 * sum_c (gpad[c,h+i-1,w+j-1] - g[c,h,w])^2)
__global__ __launch_bounds__(256)
void kfac_kernel(const float* CK guide) {
    const int tid = threadIdx.x;
    const int b = blockIdx.z;
    const int H0 = (blockIdx.x >> 3) * 16;
    const int W0 = (blockIdx.x & 7) * 16;
    __shared__ float gs[16][18][19];
    const int r  = tid >> 4;
    const int sc = tid & 15;
    float acc[9];
#pragma unroll
    for (int k = 0; k < 9; k++) acc[k] = 0.f;

    for (int ch = 0; ch < 8; ch++) {
        const int c0 = ch * 16;
        for (int e = tid; e < 16*18*18; e += 256) {
            int col = e % 18;
            int tmp = e / 18;
            int row = tmp % 18;
            int cc  = tmp / 18;
            int gr = H0 - 1 + row, gc = W0 - 1 + col;
            float v = 0.f;
            if ((unsigned)gr < 128u && (unsigned)gc < 128u)
                v = guide[((b*128 + c0 + cc)*128 + gr)*128 + gc];
            gs[cc][row][col] = v;
        }
        __syncthreads();
#pragma unroll 1
        for (int cc = 0; cc < 16; cc++) {
            float gc0 = gs[cc][r + 1][sc + 1];
#pragma unroll
            for (int ij = 0; ij < 9; ij++) {
                int di = ij / 3, dj = ij % 3;
                float d = gs[cc][r + di][sc + dj] - gc0;
                acc[ij] += d * d;
            }
        }
        __syncthreads();
    }
#pragma unroll
    for (int ij = 0; ij < 9; ij++)
        g_kf[((b*9 + ij)*128 + H0 + r)*128 + W0 + sc] = expf(-0.5f * acc[ij]);
}

// ---------------- stage 2b: PAC main (9-tap scaled conv, f32x2) ----------------
// Block: 64 co x (16x16) spatial tile. Thread: 8co x 8pos (4 f32x2 pairs).
// ysm stride 22 (conflict-free for the (r, sc8) access pattern) + ysm_odd shifted
// copy so every tap is an aligned LDS.64.
static const int PC_YS_BYTES = 8*18*22*4;            // 12672
static const int PC_KS_BYTES = 9*16*18*4;            // 10368
static const int PC_WS_BYTES = 8*9*64*8;             // 36864 (ull pairs)
static const int PC_SMEM     = 2*PC_YS_BYTES + PC_KS_BYTES + PC_WS_BYTES;  // 72576

__global__ __launch_bounds__(256, 2)
void pac_kernel(const float* CK b2, float* CK out) {
    extern __shared__ unsigned char smem_raw[];
    float (*ysm)[18][22] = (float(*)[18][22])smem_raw;
    float (*yso)[18][22] = (float(*)[18][22])(smem_raw + PC_YS_BYTES);
    float (*ksm)[16][18] = (float(*)[16][18])(smem_raw + 2*PC_YS_BYTES);
    ull   (*wsm)[9][64]  = (ull(*)[9][64])(smem_raw + 2*PC_YS_BYTES + PC_KS_BYTES);

    const int tid = threadIdx.x;
    const int b = blockIdx.z;
    const int co0 = blockIdx.y * 64;
    const int H0 = (blockIdx.x >> 3) * 16;
    const int W0 = (blockIdx.x & 7) * 16;

    const int cg8 = tid >> 5;
    const int pg  = tid & 31;
    const int r   = pg >> 1;           // 0..15
    const int sc8 = (pg & 1) * 8;      // 0,8

    // gaussian factors for tile (once)
    for (int e = tid; e < 9*256; e += 256) {
        int cc = e & 255;
        int ij = e >> 8;
        int rr = cc >> 4, col = cc & 15;
        ksm[ij][rr][col] = g_kf[((b*9 + ij)*128 + H0 + rr)*128 + W0 + col];
    }

    ull acc[8][4];
#pragma unroll
    for (int a = 0; a < 8; a++)
#pragma unroll
        for (int q = 0; q < 4; q++) acc[a][q] = 0ull;

    for (int ch = 0; ch < 16; ch++) {
        const int c0 = ch * 8;
        // y halo tile; dual store: ysm + shifted copy
        for (int e = tid; e < 8*18*18; e += 256) {
            int col = e % 18;
            int tmp = e / 18;
            int row = tmp % 18;
            int cc  = tmp / 18;
            int gr = H0 - 1 + row, gc = W0 - 1 + col;
            float v = 0.f;
            if ((unsigned)gr < 128u && (unsigned)gc < 128u)
                v = g_y[((b*128 + c0 + cc)*128 + gr)*128 + gc];
            ysm[cc][row][col] = v;
            if (col >= 1) yso[cc][row][col - 1] = v;
        }
        // duplicated weight pairs
        {
            const ull* wsrc = ((const ull*)g_w2d) + (size_t)(c0*9)*128 + co0;
            for (int e = tid; e < 8*9*64; e += 256) {
                int ol = e & 63;
                int ij = (e >> 6) % 9;
                int cc = e / (9*64);
                wsm[cc][ij][ol] = wsrc[((size_t)cc*9 + ij)*128 + ol];
            }
        }
        __syncthreads();

#pragma unroll 1
        for (int ij = 0; ij < 9; ij++) {
            const int di = ij / 3, dj = ij % 3;
            ull kp[4];
#pragma unroll
            for (int q = 0; q < 4; q++)
                kp[q] = *(const ull*)&ksm[ij][r][sc8 + 2*q];
#pragma unroll
            for (int cc = 0; cc < 8; cc++) {
                // all-aligned tap loads: dj==1 reads the shifted copy
                const ull* ysrc = (dj == 1)
                    ? (const ull*)&yso[cc][r + di][sc8]
                    : (const ull*)&ysm[cc][r + di][sc8 + dj];
                ull t[4];
#pragma unroll
                for (int q = 0; q < 4; q++)
                    t[q] = mul2(ysrc[q], kp[q]);
#pragma unroll
                for (int cg = 0; cg < 8; cg++) {
                    ull w = wsm[cc][ij][cg8*8 + cg];   // broadcast LDS.64
#pragma unroll
                    for (int q = 0; q < 4; q++)
                        ffma2(acc[cg][q], w, t[q]);
                }
            }
        }
        __syncthreads();
    }

    // epilogue: out = acc + b2 (STG.64 pairs)
#pragma unroll
    for (int cg = 0; cg < 8; cg++) {
        int co = co0 + cg8*8 + cg;
        float bv = b2[co];
        ull bvd = pack2(bv, bv);
        float* dst = &out[((size_t)(b*128 + co)*128 + H0 + r)*128 + W0 + sc8];
#pragma unroll
        for (int q = 0; q < 4; q++)
            *(ull*)(dst + 2*q) = add2(acc[cg][q], bvd);
    }
}

// ---------------- launch ----------------
extern "C" void kernel_launch(void* const* d_in, const int* in_sizes, int n_in,
                              void* d_out, int out_size) {
    const float* x     = (const float*)d_in[0];
    const float* guide = (const float*)d_in[1];
    const float* w1    = (const float*)d_in[2];
    const float* b1    = (const float*)d_in[3];
    const float* w2    = (const float*)d_in[4];
    const float* b2    = (const float*)d_in[5];
    float* out = (float*)d_out;

    cudaFuncSetAttribute(deconv_kernel, cudaFuncAttributeMaxDynamicSharedMemorySize, DC_SMEM);
    cudaFuncSetAttribute(pac_kernel,    cudaFuncAttributeMaxDynamicSharedMemorySize, PC_SMEM);

    prep_weights_kernel<<<(4*256*128*4 + 255)/256, 256>>>(w1, w2);
    deconv_kernel<<<dim3(16, 8, 4), 256, DC_SMEM>>>(x, b1);
    kfac_kernel<<<dim3(64, 1, 4), 256>>>(guide);
    pac_kernel<<<dim3(64, 2, 4), 256, PC_SMEM>>>(b2, out);
}